// round 1
// baseline (speedup 1.0000x reference)
#include <cuda_runtime.h>
#include <math.h>

// Problem dimensions (fixed by the reference).
static const int cNS  = 8192;   // sentences
static const int cNK  = 8192;   // knowledge rows
static const int cHID = 1024;   // hidden (== SENT)
static const int cKED = 2048;   // knowledge embedding dim (2*hidden)
static const int CHUNKS = 8;    // softmax row-chunks for pass 1

// Scratch (allocation-free: __device__ globals).
__device__ float g_S[(size_t)cNS * cHID];        // 32 MB
__device__ float g_K[(size_t)cNK * cHID];        // 32 MB
__device__ float g_pm[CHUNKS * cNK];
__device__ float g_ps[CHUNKS * cNK];
__device__ float g_m[cNK];
__device__ float g_rs[cNK];

// ---------------------------------------------------------------------------
// SGEMM: C[M,N] = A[M,K] * op(B) (+ bias[n])
//   BT=true : B is [N,K] row-major (C = A * B^T)
//   BT=false: B is [K,N] row-major (C = A * B)
// Tiles: 128x128x16, 256 threads, 8x8 accumulators per thread.
// All of M,N divisible by 128 and K by 16 (guaranteed by problem shapes).
// ---------------------------------------------------------------------------
template <bool BT, bool BIAS>
__global__ __launch_bounds__(256, 2)
void sgemm_kernel(const float* __restrict__ A, const float* __restrict__ B,
                  const float* __restrict__ bias, float* __restrict__ C,
                  int M, int N, int K)
{
    const int BM = 128, BN = 128, BK = 16;
    __shared__ __align__(16) float As[BK][BM];
    __shared__ __align__(16) float Bs[BK][BN];

    const int tid = threadIdx.x;
    const int bm = blockIdx.y, bn = blockIdx.x;

    const float* Ab = A + (size_t)bm * BM * K;
    const float* Bb = BT ? (B + (size_t)bn * BN * K) : (B + bn * BN);

    float4 pa[2], pb[2];

    // Prefetch tile 0 into registers.
    {
        const int k0 = 0;
#pragma unroll
        for (int u = 0; u < 2; ++u) {
            int q = tid + u * 256;
            int row = q >> 2, kq = (q & 3) << 2;
            pa[u] = *(const float4*)(Ab + (size_t)row * K + k0 + kq);
        }
#pragma unroll
        for (int u = 0; u < 2; ++u) {
            int q = tid + u * 256;
            if (BT) {
                int row = q >> 2, kq = (q & 3) << 2;
                pb[u] = *(const float4*)(Bb + (size_t)row * K + k0 + kq);
            } else {
                int kk = q >> 5, n4 = (q & 31) << 2;
                pb[u] = *(const float4*)(Bb + (size_t)(k0 + kk) * N + n4);
            }
        }
    }

    const int r = tid >> 4, c = tid & 15;
    const int r8 = r * 8, c8 = c * 8;
    float acc[8][8];
#pragma unroll
    for (int i = 0; i < 8; ++i)
#pragma unroll
        for (int j = 0; j < 8; ++j) acc[i][j] = 0.f;

    const int T = K / BK;
    for (int kt = 0; kt < T; ++kt) {
        // Store prefetched tile to smem.
#pragma unroll
        for (int u = 0; u < 2; ++u) {
            int q = tid + u * 256;
            int row = q >> 2, kq = (q & 3) << 2;
            As[kq + 0][row] = pa[u].x;
            As[kq + 1][row] = pa[u].y;
            As[kq + 2][row] = pa[u].z;
            As[kq + 3][row] = pa[u].w;
        }
#pragma unroll
        for (int u = 0; u < 2; ++u) {
            int q = tid + u * 256;
            if (BT) {
                int row = q >> 2, kq = (q & 3) << 2;
                Bs[kq + 0][row] = pb[u].x;
                Bs[kq + 1][row] = pb[u].y;
                Bs[kq + 2][row] = pb[u].z;
                Bs[kq + 3][row] = pb[u].w;
            } else {
                int kk = q >> 5, n4 = (q & 31) << 2;
                *(float4*)(&Bs[kk][n4]) = pb[u];
            }
        }
        __syncthreads();

        // Prefetch next tile while computing this one.
        if (kt + 1 < T) {
            const int k0 = (kt + 1) * BK;
#pragma unroll
            for (int u = 0; u < 2; ++u) {
                int q = tid + u * 256;
                int row = q >> 2, kq = (q & 3) << 2;
                pa[u] = *(const float4*)(Ab + (size_t)row * K + k0 + kq);
            }
#pragma unroll
            for (int u = 0; u < 2; ++u) {
                int q = tid + u * 256;
                if (BT) {
                    int row = q >> 2, kq = (q & 3) << 2;
                    pb[u] = *(const float4*)(Bb + (size_t)row * K + k0 + kq);
                } else {
                    int kk = q >> 5, n4 = (q & 31) << 2;
                    pb[u] = *(const float4*)(Bb + (size_t)(k0 + kk) * N + n4);
                }
            }
        }

        // Compute.
#pragma unroll
        for (int kk = 0; kk < BK; ++kk) {
            float a[8], b[8];
            *(float4*)(a)     = *(const float4*)(&As[kk][r8]);
            *(float4*)(a + 4) = *(const float4*)(&As[kk][r8 + 4]);
            *(float4*)(b)     = *(const float4*)(&Bs[kk][c8]);
            *(float4*)(b + 4) = *(const float4*)(&Bs[kk][c8 + 4]);
#pragma unroll
            for (int i = 0; i < 8; ++i)
#pragma unroll
                for (int j = 0; j < 8; ++j)
                    acc[i][j] = fmaf(a[i], b[j], acc[i][j]);
        }
        __syncthreads();
    }

    // Epilogue.
    const int row0 = bm * BM + r8;
    const int col0 = bn * BN + c8;
    float bv[8];
    if (BIAS) {
        *(float4*)(bv)     = *(const float4*)(&bias[col0]);
        *(float4*)(bv + 4) = *(const float4*)(&bias[col0 + 4]);
    } else {
#pragma unroll
        for (int j = 0; j < 8; ++j) bv[j] = 0.f;
    }
#pragma unroll
    for (int i = 0; i < 8; ++i) {
        size_t off = (size_t)(row0 + i) * N + col0;
        float4 v0, v1;
        v0.x = acc[i][0] + bv[0]; v0.y = acc[i][1] + bv[1];
        v0.z = acc[i][2] + bv[2]; v0.w = acc[i][3] + bv[3];
        v1.x = acc[i][4] + bv[4]; v1.y = acc[i][5] + bv[5];
        v1.z = acc[i][6] + bv[6]; v1.w = acc[i][7] + bv[7];
        *(float4*)(C + off)     = v0;
        *(float4*)(C + off + 4) = v1;
    }
}

// ---------------------------------------------------------------------------
// Column-wise softmax (axis=0 over the Ns dimension) on scores [Ns, Nk].
// Pass 1: per (row-chunk, column) online max/sum.
// ---------------------------------------------------------------------------
__global__ void softmax_pass1(const float* __restrict__ sc)
{
    const int j = blockIdx.x * 256 + threadIdx.x;
    const int chunk = blockIdx.y;
    const int rows = cNS / CHUNKS;
    const int i0 = chunk * rows;
    float m = -1e30f, s = 0.f;
#pragma unroll 4
    for (int i = 0; i < rows; ++i) {
        float x = sc[(size_t)(i0 + i) * cNK + j];
        float nm = fmaxf(m, x);
        s = s * expf(m - nm) + expf(x - nm);
        m = nm;
    }
    g_pm[chunk * cNK + j] = m;
    g_ps[chunk * cNK + j] = s;
}

// Pass 2: reduce chunk partials per column.
__global__ void softmax_pass2()
{
    const int j = blockIdx.x * 256 + threadIdx.x;
    float m = -1e30f, s = 0.f;
#pragma unroll
    for (int c = 0; c < CHUNKS; ++c) {
        float pm = g_pm[c * cNK + j];
        float ps = g_ps[c * cNK + j];
        float nm = fmaxf(m, pm);
        s = s * expf(m - nm) + ps * expf(pm - nm);
        m = nm;
    }
    g_m[j] = m;
    g_rs[j] = 1.f / s;
}

// Pass 3: normalize in place (float4 per thread).
__global__ void softmax_pass3(float* __restrict__ sc)
{
    const int j4 = (blockIdx.x * 256 + threadIdx.x) * 4;
    const size_t i = blockIdx.y;
    float4 x = *(float4*)(&sc[i * cNK + j4]);
    float4 m = *(const float4*)(&g_m[j4]);
    float4 rs = *(const float4*)(&g_rs[j4]);
    x.x = expf(x.x - m.x) * rs.x;
    x.y = expf(x.y - m.y) * rs.y;
    x.z = expf(x.z - m.z) * rs.z;
    x.w = expf(x.w - m.w) * rs.w;
    *(float4*)(&sc[i * cNK + j4]) = x;
}

// ---------------------------------------------------------------------------
// Launch
// ---------------------------------------------------------------------------
extern "C" void kernel_launch(void* const* d_in, const int* in_sizes, int n_in,
                              void* d_out, int out_size)
{
    const float* Xs = (const float*)d_in[0];  // [8192, 1024]
    const float* Xk = (const float*)d_in[1];  // [8192, 2048]
    const float* Ws = (const float*)d_in[2];  // [1024, 1024]
    const float* bs = (const float*)d_in[3];  // [1024]
    const float* Wk = (const float*)d_in[4];  // [1024, 2048]
    const float* bk = (const float*)d_in[5];  // [1024]

    float* attns = (float*)d_out;                       // [8192, 8192]
    float* fused = attns + (size_t)cNS * cNK;           // [8192, 2048]

    float *dS = nullptr, *dK = nullptr;
    cudaGetSymbolAddress((void**)&dS, g_S);
    cudaGetSymbolAddress((void**)&dK, g_K);

    // S = Xs @ Ws^T + bs   [8192, 1024]
    sgemm_kernel<true, true><<<dim3(cHID / 128, cNS / 128), 256>>>(
        Xs, Ws, bs, dS, cNS, cHID, 1024);

    // K = Xk @ Wk^T + bk   [8192, 1024]
    sgemm_kernel<true, true><<<dim3(cHID / 128, cNK / 128), 256>>>(
        Xk, Wk, bk, dK, cNK, cHID, 2048);

    // scores = S @ K^T     [8192, 8192]  (written into attns region)
    sgemm_kernel<true, false><<<dim3(cNK / 128, cNS / 128), 256>>>(
        dS, dK, nullptr, attns, cNS, cNK, cHID);

    // softmax over axis 0 (columns), in place
    softmax_pass1<<<dim3(cNK / 256, CHUNKS), 256>>>(attns);
    softmax_pass2<<<cNK / 256, 256>>>();
    softmax_pass3<<<dim3(cNK / 1024, cNS), 256>>>(attns);

    // fused = attns @ V    [8192, 2048], V = Xk
    sgemm_kernel<false, false><<<dim3(cKED / 128, cNS / 128), 256>>>(
        attns, Xk, nullptr, fused, cNS, cKED, cNK);
}

// round 3
// speedup vs baseline: 2.0722x; 2.0722x over previous
#include <cuda_runtime.h>
#include <cuda_bf16.h>
#include <stdint.h>

// ---------------------------------------------------------------------------
// Problem dims
// ---------------------------------------------------------------------------
static const int cNS  = 8192;
static const int cNK  = 8192;
static const int cHID = 1024;
static const int cKED = 2048;
static const int CHUNKS = 8;   // softmax row chunks

// ---------------------------------------------------------------------------
// Scratch (__device__ globals; allocation-free)
// ---------------------------------------------------------------------------
__device__ __nv_bfloat16 g_Xs_h[(size_t)cNS * cHID];
__device__ __nv_bfloat16 g_Xs_l[(size_t)cNS * cHID];
__device__ __nv_bfloat16 g_Xk_h[(size_t)cNK * cKED];
__device__ __nv_bfloat16 g_Xk_l[(size_t)cNK * cKED];
__device__ __nv_bfloat16 g_Ws_h[(size_t)cHID * cHID];
__device__ __nv_bfloat16 g_Ws_l[(size_t)cHID * cHID];
__device__ __nv_bfloat16 g_Wk_h[(size_t)cHID * cKED];
__device__ __nv_bfloat16 g_Wk_l[(size_t)cHID * cKED];
__device__ __nv_bfloat16 g_S_h[(size_t)cNS * cHID];
__device__ __nv_bfloat16 g_S_l[(size_t)cNS * cHID];
__device__ __nv_bfloat16 g_K_h[(size_t)cNK * cHID];
__device__ __nv_bfloat16 g_K_l[(size_t)cNK * cHID];
__device__ __nv_bfloat16 g_VT_h[(size_t)cKED * cNK];   // V^T  [2048, 8192]
__device__ __nv_bfloat16 g_VT_l[(size_t)cKED * cNK];
__device__ __nv_bfloat16 g_At_h[(size_t)cNS * cNK];    // attns split planes
__device__ __nv_bfloat16 g_At_l[(size_t)cNS * cNK];
__device__ float g_pm[CHUNKS * cNK];
__device__ float g_ps[CHUNKS * cNK];
__device__ float g_m[cNK];
__device__ float g_rs[cNK];

// ---------------------------------------------------------------------------
// Helpers
// ---------------------------------------------------------------------------
__device__ __forceinline__ uint32_t smem_to_u32(const void* p) {
    uint32_t a;
    asm("{ .reg .u64 t; cvta.to.shared.u64 t, %1; cvt.u32.u64 %0, t; }"
        : "=r"(a) : "l"(p));
    return a;
}

__device__ __forceinline__ void cp_async16(uint32_t smem_addr, const void* gptr) {
    asm volatile("cp.async.cg.shared.global [%0], [%1], 16;\n"
                 :: "r"(smem_addr), "l"(__cvta_generic_to_global(gptr)));
}
__device__ __forceinline__ void cp_commit() {
    asm volatile("cp.async.commit_group;\n" ::: "memory");
}
template <int N>
__device__ __forceinline__ void cp_wait() {
    asm volatile("cp.async.wait_group %0;\n" :: "n"(N) : "memory");
}

__device__ __forceinline__ void ldsm_x4(uint32_t (&r)[4], uint32_t addr) {
    asm volatile("ldmatrix.sync.aligned.m8n8.x4.shared.b16 {%0,%1,%2,%3}, [%4];\n"
                 : "=r"(r[0]), "=r"(r[1]), "=r"(r[2]), "=r"(r[3]) : "r"(addr));
}

__device__ __forceinline__ void mma16816(float (&c)[4], const uint32_t (&a)[4],
                                         uint32_t b0, uint32_t b1) {
    asm volatile(
        "mma.sync.aligned.m16n8k16.row.col.f32.bf16.bf16.f32 "
        "{%0,%1,%2,%3}, {%4,%5,%6,%7}, {%8,%9}, {%0,%1,%2,%3};\n"
        : "+f"(c[0]), "+f"(c[1]), "+f"(c[2]), "+f"(c[3])
        : "r"(a[0]), "r"(a[1]), "r"(a[2]), "r"(a[3]), "r"(b0), "r"(b1));
}

__device__ __forceinline__ void split1(float x, __nv_bfloat16& h, __nv_bfloat16& l) {
    h = __float2bfloat16(x);
    l = __float2bfloat16(x - __bfloat162float(h));
}

// ---------------------------------------------------------------------------
// Split / transpose-split preprocessing
// ---------------------------------------------------------------------------
__global__ void split_kernel(const float* __restrict__ in,
                             __nv_bfloat16* __restrict__ hi,
                             __nv_bfloat16* __restrict__ lo, size_t n) {
    size_t i = ((size_t)blockIdx.x * 256 + threadIdx.x) * 4;
    if (i >= n) return;
    float4 v = *(const float4*)(in + i);
    __nv_bfloat16 h0, h1, h2, h3, l0, l1, l2, l3;
    split1(v.x, h0, l0); split1(v.y, h1, l1);
    split1(v.z, h2, l2); split1(v.w, h3, l3);
    *(__nv_bfloat162*)(hi + i)     = __nv_bfloat162(h0, h1);
    *(__nv_bfloat162*)(hi + i + 2) = __nv_bfloat162(h2, h3);
    *(__nv_bfloat162*)(lo + i)     = __nv_bfloat162(l0, l1);
    *(__nv_bfloat162*)(lo + i + 2) = __nv_bfloat162(l2, l3);
}

__global__ void transpose_split_kernel(const float* __restrict__ in,
                                       __nv_bfloat16* __restrict__ hi,
                                       __nv_bfloat16* __restrict__ lo,
                                       int R, int C) {
    __shared__ float t[32][33];
    int c0 = blockIdx.x * 32, r0 = blockIdx.y * 32;
    int tx = threadIdx.x, ty = threadIdx.y;
#pragma unroll
    for (int j = 0; j < 4; ++j)
        t[ty + j * 8][tx] = in[(size_t)(r0 + ty + j * 8) * C + c0 + tx];
    __syncthreads();
#pragma unroll
    for (int j = 0; j < 4; ++j) {
        float v = t[tx][ty + j * 8];
        __nv_bfloat16 h, l; split1(v, h, l);
        size_t off = (size_t)(c0 + ty + j * 8) * R + r0 + tx;
        hi[off] = h; lo[off] = l;
    }
}

// ---------------------------------------------------------------------------
// Split-bf16 HMMA GEMM: C[M,N] = (Ah+Al)[M,K] * (Bh+Bl)[N,K]^T (+ bias)
// 128x128 CTA tile, BK=32, 3-stage cp.async pipeline, 8 warps (2x4),
// warp tile 64x32, mma.sync m16n8k16 bf16, 3 passes (AhBh, AhBl, AlBh).
// SMEM rows padded to 80B -> conflict-free ldmatrix.
// ---------------------------------------------------------------------------
static const int ROWB    = 80;                 // 64B data + 16B pad
static const int TILE_B  = 128 * ROWB;         // 10240 B per plane-tile
static const int STAGE_B = 4 * TILE_B;         // Ah, Al, Bh, Bl
static const int STAGES  = 3;
static const int SMEM_NEED = STAGES * STAGE_B; // 122880

template <bool BIAS, bool SPLIT>
__global__ __launch_bounds__(256, 1)
void mma_gemm(const __nv_bfloat16* __restrict__ Ah, const __nv_bfloat16* __restrict__ Al,
              const __nv_bfloat16* __restrict__ Bh, const __nv_bfloat16* __restrict__ Bl,
              const float* __restrict__ bias,
              float* __restrict__ C,
              __nv_bfloat16* __restrict__ Ch, __nv_bfloat16* __restrict__ Cl,
              int M, int N, int K)
{
    extern __shared__ char sm[];
    const uint32_t sbase = smem_to_u32(sm);

    const int tid = threadIdx.x;
    const int wid = tid >> 5, lane = tid & 31;
    const int wm = wid >> 2, wn = wid & 3;      // 2 x 4 warp grid
    const int row0 = blockIdx.y * 128, col0 = blockIdx.x * 128;

    const __nv_bfloat16* srcs[4] = {
        Ah + (size_t)row0 * K, Al + (size_t)row0 * K,
        Bh + (size_t)col0 * K, Bl + (size_t)col0 * K };

    const int NT = K >> 5;   // k32 stages

    // ---- async load of one stage (2048 x 16B chunks, 8 per thread) ----
    auto issue_loads = [&](int kt, int s) {
        const int k0 = kt << 5;
#pragma unroll
        for (int i = 0; i < 8; ++i) {
            int q = tid + i * 256;
            int t = q >> 9, idx = q & 511;
            int row = idx >> 2, c = idx & 3;
            const __nv_bfloat16* g = srcs[t] + (size_t)row * K + k0 + c * 8;
            uint32_t d = sbase + s * STAGE_B + t * TILE_B + row * ROWB + c * 16;
            cp_async16(d, g);
        }
    };

    issue_loads(0, 0); cp_commit();
    issue_loads(1, 1); cp_commit();

    float acc[4][4][4];
#pragma unroll
    for (int i = 0; i < 4; ++i)
#pragma unroll
        for (int j = 0; j < 4; ++j)
#pragma unroll
            for (int v = 0; v < 4; ++v) acc[i][j][v] = 0.f;

    const int lrow = lane & 15, lcol = lane >> 4;

    for (int kt = 0; kt < NT; ++kt) {
        const int s = kt % 3;
        cp_wait<1>();
        __syncthreads();
        if (kt + 2 < NT) issue_loads(kt + 2, (kt + 2) % 3);
        cp_commit();

#pragma unroll
        for (int ks = 0; ks < 2; ++ks) {
            uint32_t ah[4][4], al[4][4], bh[2][4], bl[2][4];
            const uint32_t abase = sbase + s * STAGE_B
                + (wm * 64 + lrow) * ROWB + ks * 32 + lcol * 16;
#pragma unroll
            for (int mi = 0; mi < 4; ++mi) {
                ldsm_x4(ah[mi], abase + mi * 16 * ROWB);
                ldsm_x4(al[mi], abase + mi * 16 * ROWB + TILE_B);
            }
            const uint32_t bbase = sbase + s * STAGE_B + 2 * TILE_B
                + (wn * 32 + lrow) * ROWB + ks * 32 + lcol * 16;
#pragma unroll
            for (int bj = 0; bj < 2; ++bj) {
                ldsm_x4(bh[bj], bbase + bj * 16 * ROWB);
                ldsm_x4(bl[bj], bbase + bj * 16 * ROWB + TILE_B);
            }
#pragma unroll
            for (int mi = 0; mi < 4; ++mi) {
#pragma unroll
                for (int jn = 0; jn < 4; ++jn) {
                    const int bj = jn >> 1, hf = jn & 1;
                    mma16816(acc[mi][jn], ah[mi], bh[bj][hf], bh[bj][hf + 2]);
                    mma16816(acc[mi][jn], ah[mi], bl[bj][hf], bl[bj][hf + 2]);
                    mma16816(acc[mi][jn], al[mi], bh[bj][hf], bh[bj][hf + 2]);
                }
            }
        }
    }

    // ---- epilogue ----
    const int g = lane >> 2, cq = (lane & 3) * 2;
#pragma unroll
    for (int mi = 0; mi < 4; ++mi) {
#pragma unroll
        for (int jn = 0; jn < 4; ++jn) {
            const int r0w = row0 + wm * 64 + mi * 16 + g;
            const int cc = col0 + wn * 32 + jn * 8 + cq;
            float v0 = acc[mi][jn][0], v1 = acc[mi][jn][1];
            float v2 = acc[mi][jn][2], v3 = acc[mi][jn][3];
            if (BIAS) {
                float b0 = bias[cc], b1 = bias[cc + 1];
                v0 += b0; v1 += b1; v2 += b0; v3 += b1;
            }
            if (SPLIT) {
                __nv_bfloat16 h0, h1, h2, h3, l0, l1, l2, l3;
                split1(v0, h0, l0); split1(v1, h1, l1);
                split1(v2, h2, l2); split1(v3, h3, l3);
                size_t o0 = (size_t)r0w * N + cc;
                size_t o1 = (size_t)(r0w + 8) * N + cc;
                *(__nv_bfloat162*)(Ch + o0) = __nv_bfloat162(h0, h1);
                *(__nv_bfloat162*)(Cl + o0) = __nv_bfloat162(l0, l1);
                *(__nv_bfloat162*)(Ch + o1) = __nv_bfloat162(h2, h3);
                *(__nv_bfloat162*)(Cl + o1) = __nv_bfloat162(l2, l3);
            } else {
                *(float2*)(C + (size_t)r0w * N + cc)       = make_float2(v0, v1);
                *(float2*)(C + (size_t)(r0w + 8) * N + cc) = make_float2(v2, v3);
            }
        }
    }
}

// ---------------------------------------------------------------------------
// Column softmax (axis 0) on scores [Ns, Nk]
// ---------------------------------------------------------------------------
__global__ void softmax_pass1(const float* __restrict__ sc) {
    const int j4 = (blockIdx.x * 256 + threadIdx.x) * 4;
    const int chunk = blockIdx.y;
    const int rows = cNS / CHUNKS;
    const size_t i0 = (size_t)chunk * rows;
    float m0 = -1e30f, m1 = -1e30f, m2 = -1e30f, m3 = -1e30f;
    float s0 = 0.f, s1 = 0.f, s2 = 0.f, s3 = 0.f;
#pragma unroll 4
    for (int i = 0; i < rows; ++i) {
        float4 x = *(const float4*)(sc + (i0 + i) * cNK + j4);
        float n0 = fmaxf(m0, x.x); s0 = s0 * __expf(m0 - n0) + __expf(x.x - n0); m0 = n0;
        float n1 = fmaxf(m1, x.y); s1 = s1 * __expf(m1 - n1) + __expf(x.y - n1); m1 = n1;
        float n2 = fmaxf(m2, x.z); s2 = s2 * __expf(m2 - n2) + __expf(x.z - n2); m2 = n2;
        float n3 = fmaxf(m3, x.w); s3 = s3 * __expf(m3 - n3) + __expf(x.w - n3); m3 = n3;
    }
    g_pm[chunk * cNK + j4 + 0] = m0; g_ps[chunk * cNK + j4 + 0] = s0;
    g_pm[chunk * cNK + j4 + 1] = m1; g_ps[chunk * cNK + j4 + 1] = s1;
    g_pm[chunk * cNK + j4 + 2] = m2; g_ps[chunk * cNK + j4 + 2] = s2;
    g_pm[chunk * cNK + j4 + 3] = m3; g_ps[chunk * cNK + j4 + 3] = s3;
}

__global__ void softmax_pass2() {
    const int j = blockIdx.x * 256 + threadIdx.x;
    float m = -1e30f, s = 0.f;
#pragma unroll
    for (int c = 0; c < CHUNKS; ++c) {
        float pm = g_pm[c * cNK + j];
        float ps = g_ps[c * cNK + j];
        float nm = fmaxf(m, pm);
        s = s * __expf(m - nm) + ps * __expf(pm - nm);
        m = nm;
    }
    g_m[j] = m;
    g_rs[j] = 1.f / s;
}

__global__ void softmax_pass3(float* __restrict__ sc,
                              __nv_bfloat16* __restrict__ hi,
                              __nv_bfloat16* __restrict__ lo) {
    const int j4 = (blockIdx.x * 256 + threadIdx.x) * 4;
    const size_t i = blockIdx.y;
    float4 x = *(float4*)(sc + i * cNK + j4);
    float4 m = *(const float4*)(&g_m[j4]);
    float4 rs = *(const float4*)(&g_rs[j4]);
    x.x = __expf(x.x - m.x) * rs.x;
    x.y = __expf(x.y - m.y) * rs.y;
    x.z = __expf(x.z - m.z) * rs.z;
    x.w = __expf(x.w - m.w) * rs.w;
    *(float4*)(sc + i * cNK + j4) = x;
    __nv_bfloat16 h0, h1, h2, h3, l0, l1, l2, l3;
    split1(x.x, h0, l0); split1(x.y, h1, l1);
    split1(x.z, h2, l2); split1(x.w, h3, l3);
    size_t off = i * cNK + j4;
    *(__nv_bfloat162*)(hi + off)     = __nv_bfloat162(h0, h1);
    *(__nv_bfloat162*)(hi + off + 2) = __nv_bfloat162(h2, h3);
    *(__nv_bfloat162*)(lo + off)     = __nv_bfloat162(l0, l1);
    *(__nv_bfloat162*)(lo + off + 2) = __nv_bfloat162(l2, l3);
}

// ---------------------------------------------------------------------------
// Launch
// ---------------------------------------------------------------------------
extern "C" void kernel_launch(void* const* d_in, const int* in_sizes, int n_in,
                              void* d_out, int out_size)
{
    const float* Xs = (const float*)d_in[0];
    const float* Xk = (const float*)d_in[1];
    const float* Ws = (const float*)d_in[2];
    const float* bs = (const float*)d_in[3];
    const float* Wk = (const float*)d_in[4];
    const float* bk = (const float*)d_in[5];

    float* attns = (float*)d_out;
    float* fused = attns + (size_t)cNS * cNK;

    __nv_bfloat16 *Xsh, *Xsl, *Xkh, *Xkl, *Wsh, *Wsl, *Wkh, *Wkl;
    __nv_bfloat16 *Sh, *Sl, *Kh, *Kl, *VTh, *VTl, *Ath, *Atl;
    cudaGetSymbolAddress((void**)&Xsh, g_Xs_h); cudaGetSymbolAddress((void**)&Xsl, g_Xs_l);
    cudaGetSymbolAddress((void**)&Xkh, g_Xk_h); cudaGetSymbolAddress((void**)&Xkl, g_Xk_l);
    cudaGetSymbolAddress((void**)&Wsh, g_Ws_h); cudaGetSymbolAddress((void**)&Wsl, g_Ws_l);
    cudaGetSymbolAddress((void**)&Wkh, g_Wk_h); cudaGetSymbolAddress((void**)&Wkl, g_Wk_l);
    cudaGetSymbolAddress((void**)&Sh,  g_S_h);  cudaGetSymbolAddress((void**)&Sl,  g_S_l);
    cudaGetSymbolAddress((void**)&Kh,  g_K_h);  cudaGetSymbolAddress((void**)&Kl,  g_K_l);
    cudaGetSymbolAddress((void**)&VTh, g_VT_h); cudaGetSymbolAddress((void**)&VTl, g_VT_l);
    cudaGetSymbolAddress((void**)&Ath, g_At_h); cudaGetSymbolAddress((void**)&Atl, g_At_l);

    cudaFuncSetAttribute(mma_gemm<true, true>,
                         cudaFuncAttributeMaxDynamicSharedMemorySize, SMEM_NEED);
    cudaFuncSetAttribute(mma_gemm<false, false>,
                         cudaFuncAttributeMaxDynamicSharedMemorySize, SMEM_NEED);

    // Split inputs
    {
        size_t n;
        n = (size_t)cNS * cHID; split_kernel<<<(unsigned)(n / 1024), 256>>>(Xs, Xsh, Xsl, n);
        n = (size_t)cNK * cKED; split_kernel<<<(unsigned)(n / 1024), 256>>>(Xk, Xkh, Xkl, n);
        n = (size_t)cHID * cHID; split_kernel<<<(unsigned)(n / 1024), 256>>>(Ws, Wsh, Wsl, n);
        n = (size_t)cHID * cKED; split_kernel<<<(unsigned)(n / 1024), 256>>>(Wk, Wkh, Wkl, n);
    }
    // V^T split
    transpose_split_kernel<<<dim3(cKED / 32, cNK / 32), dim3(32, 8)>>>(
        Xk, VTh, VTl, cNK, cKED);

    // S = Xs @ Ws^T + bs  -> split planes  [8192, 1024]
    mma_gemm<true, true><<<dim3(cHID / 128, cNS / 128), 256, SMEM_NEED>>>(
        Xsh, Xsl, Wsh, Wsl, bs, nullptr, Sh, Sl, cNS, cHID, cHID);

    // K = Xk @ Wk^T + bk  -> split planes  [8192, 1024]
    mma_gemm<true, true><<<dim3(cHID / 128, cNK / 128), 256, SMEM_NEED>>>(
        Xkh, Xkl, Wkh, Wkl, bk, nullptr, Kh, Kl, cNK, cHID, cKED);

    // scores = S @ K^T -> fp32 into attns region  [8192, 8192]
    mma_gemm<false, false><<<dim3(cNK / 128, cNS / 128), 256, SMEM_NEED>>>(
        Sh, Sl, Kh, Kl, nullptr, attns, nullptr, nullptr, cNS, cNK, cHID);

    // softmax over axis 0, in place; emit split planes
    softmax_pass1<<<dim3(cNK / 1024, CHUNKS), 256>>>(attns);
    softmax_pass2<<<cNK / 256, 256>>>();
    softmax_pass3<<<dim3(cNK / 1024, cNS), 256>>>(attns, Ath, Atl);

    // fused = attns @ V = attns @ (V^T)^T  [8192, 2048]
    mma_gemm<false, false><<<dim3(cKED / 128, cNS / 128), 256, SMEM_NEED>>>(
        Ath, Atl, VTh, VTl, nullptr, fused, nullptr, nullptr, cNS, cKED, cNK);
}